// round 8
// baseline (speedup 1.0000x reference)
#include <cuda_runtime.h>
#include <cuda_fp16.h>
#include <cstdint>
#include <cstddef>

#define NN 50000
#define NE 800000
#define DIN 128
#define DHID 512
#define DOUT 256

// ---------------------------------------------------------------------------
// Scratch (device globals — no runtime allocation)
// ---------------------------------------------------------------------------
__device__ __half g_xhi[(size_t)NN * DIN];       // (x+agg) split hi
__device__ __half g_xlo[(size_t)NN * DIN];       // (x+agg) residual
__device__ __half g_mhi[(size_t)NN * DHID];      // hmid hi
__device__ __half g_mlo[(size_t)NN * DHID];      // hmid residual
__device__ float g_h2[(size_t)NN * DOUT];        // after layer2+act (fp32)
__device__ __half g_w1hi[(size_t)DHID * DIN];    // W1^T [N][K] fp16
__device__ __half g_w2hi[(size_t)DOUT * DHID];   // W2^T [N][K] fp16
__device__ float g_sum[DOUT];
__device__ float g_sumsq[DOUT];
__device__ float g_scale[DOUT];
__device__ float g_shift[DOUT];
__device__ int g_tile2;                          // GEMM2 dynamic tile counter
// CSR build
__device__ int g_deg[NN];
__device__ int g_off[NN + 1];
__device__ int g_cur[NN];
__device__ int g_srcs[NE];

// ---------------------------------------------------------------------------
// PTX helpers
// ---------------------------------------------------------------------------
__device__ __forceinline__ uint32_t smem_u32(const void* p) {
    uint32_t a;
    asm("{ .reg .u64 t; cvta.to.shared.u64 t, %1; cvt.u32.u64 %0, t; }"
        : "=r"(a) : "l"(p));
    return a;
}
__device__ __forceinline__ void cp_async16(uint32_t dst, const void* src, bool pred) {
    int sz = pred ? 16 : 0;
    asm volatile("cp.async.cg.shared.global [%0], [%1], 16, %2;"
                 :: "r"(dst), "l"(src), "r"(sz));
}
__device__ __forceinline__ void cp_commit() {
    asm volatile("cp.async.commit_group;" ::: "memory");
}
__device__ __forceinline__ void cp_wait0() {
    asm volatile("cp.async.wait_group 0;" ::: "memory");
}
__device__ __forceinline__ void cp_wait1() {
    asm volatile("cp.async.wait_group 1;" ::: "memory");
}
__device__ __forceinline__ void ldsm_x4(uint32_t* r, uint32_t addr) {
    asm volatile("ldmatrix.sync.aligned.m8n8.x4.shared.b16 {%0,%1,%2,%3}, [%4];"
                 : "=r"(r[0]), "=r"(r[1]), "=r"(r[2]), "=r"(r[3]) : "r"(addr));
}
__device__ __forceinline__ void hmma(float* c, const uint32_t* a, const uint32_t* b) {
    asm volatile(
        "mma.sync.aligned.m16n8k16.row.col.f32.f16.f16.f32 "
        "{%0,%1,%2,%3}, {%4,%5,%6,%7}, {%8,%9}, {%0,%1,%2,%3};"
        : "+f"(c[0]), "+f"(c[1]), "+f"(c[2]), "+f"(c[3])
        : "r"(a[0]), "r"(a[1]), "r"(a[2]), "r"(a[3]), "r"(b[0]), "r"(b[1]));
}

// ---------------------------------------------------------------------------
// 0) zero: degree counters + BN accumulators + tile counter
// ---------------------------------------------------------------------------
__global__ void k_zero() {
    int i = blockIdx.x * blockDim.x + threadIdx.x;
    if (i < NN) g_deg[i] = 0;
    if (i < DOUT) { g_sum[i] = 0.f; g_sumsq[i] = 0.f; }
    if (i == 0) g_tile2 = 0;
}

// ---------------------------------------------------------------------------
// 1) histogram of dst degrees
// ---------------------------------------------------------------------------
__global__ void k_hist(const int* __restrict__ ei) {
    int e = blockIdx.x * blockDim.x + threadIdx.x;
    if (e < NE) atomicAdd(&g_deg[ei[NE + e]], 1);
}

// ---------------------------------------------------------------------------
// 2) exclusive scan over degrees (single block)
// ---------------------------------------------------------------------------
__global__ void __launch_bounds__(1024) k_scan() {
    __shared__ int bs[1024];
    const int t = threadIdx.x;
    const int SEG = (NN + 1023) / 1024;
    int start = t * SEG;
    int stop = start + SEG < NN ? start + SEG : NN;
    int s = 0;
    for (int i = start; i < stop; i++) s += g_deg[i];
    bs[t] = s;
    __syncthreads();
    for (int d = 1; d < 1024; d <<= 1) {
        int u = (t >= d) ? bs[t - d] : 0;
        __syncthreads();
        if (t >= d) bs[t] += u;
        __syncthreads();
    }
    int run = bs[t] - s;
    for (int i = start; i < stop; i++) {
        g_off[i] = run;
        g_cur[i] = run;
        run += g_deg[i];
    }
    if (t == 1023) g_off[NN] = run;
}

// ---------------------------------------------------------------------------
// 3) bucket edges by dst
// ---------------------------------------------------------------------------
__global__ void k_bucket(const int* __restrict__ ei) {
    int e = blockIdx.x * blockDim.x + threadIdx.x;
    if (e >= NE) return;
    int dst = ei[NE + e];
    int pos = atomicAdd(&g_cur[dst], 1);
    g_srcs[pos] = ei[e];
}

// ---------------------------------------------------------------------------
// 4) aggregate: one warp per node; split hi/lo fp16
// ---------------------------------------------------------------------------
__global__ void __launch_bounds__(256) k_agg(const float* __restrict__ x) {
    int w = (blockIdx.x * blockDim.x + threadIdx.x) >> 5;
    if (w >= NN) return;
    int lane = threadIdx.x & 31;

    float4 acc = reinterpret_cast<const float4*>(x + (size_t)w * DIN)[lane];
    int beg = g_off[w], end = g_off[w + 1];
    for (int base = beg; base < end; base += 32) {
        int n = end - base;
        if (n > 32) n = 32;
        int s = (lane < n) ? g_srcs[base + lane] : 0;
        #pragma unroll 4
        for (int j = 0; j < n; j++) {
            int src = __shfl_sync(0xffffffffu, s, j);
            float4 v = reinterpret_cast<const float4*>(x + (size_t)src * DIN)[lane];
            acc.x += v.x; acc.y += v.y; acc.z += v.z; acc.w += v.w;
        }
    }
    __half hx = __float2half_rn(acc.x), hy = __float2half_rn(acc.y);
    __half hz = __float2half_rn(acc.z), hw = __float2half_rn(acc.w);
    __half lx = __float2half_rn(acc.x - __half2float(hx));
    __half ly = __float2half_rn(acc.y - __half2float(hy));
    __half lz = __float2half_rn(acc.z - __half2float(hz));
    __half lw = __float2half_rn(acc.w - __half2float(hw));
    size_t idx = (size_t)w * DIN + lane * 4;
    __half2* phi = reinterpret_cast<__half2*>(g_xhi + idx);
    __half2* plo = reinterpret_cast<__half2*>(g_xlo + idx);
    phi[0] = __halves2half2(hx, hy);
    phi[1] = __halves2half2(hz, hw);
    plo[0] = __halves2half2(lx, ly);
    plo[1] = __halves2half2(lz, lw);
}

// ---------------------------------------------------------------------------
// 5) W [K,N] -> W^T [N,K] fp16
// ---------------------------------------------------------------------------
__global__ void k_prep_w(const float* __restrict__ W, __half* __restrict__ hi,
                         int K, int N) {
    int i = blockIdx.x * blockDim.x + threadIdx.x;
    if (i >= K * N) return;
    int n = i / K, k = i % K;
    hi[i] = __float2half_rn(W[(size_t)k * N + n]);
}

// ---------------------------------------------------------------------------
// 6) GEMM1: hmid = lrelu(A @ W1^T + b1) -> fp16 hi/lo.
//    CTA 128x128, BK=32, 8 warps (4m x 2n), 3-stage ring, 2 CTAs/SM.
// ---------------------------------------------------------------------------
#define ROWB 80
#define MATB (128 * ROWB)
#define STAGEB (3 * MATB)
#define SM_AHI 0
#define SM_ALO MATB
#define SM_BHI (2 * MATB)
#define NSTAGE 3
#define G1_SMEM (NSTAGE * STAGEB)    // 92160

__global__ void __launch_bounds__(256, 2)
k_gemm1(const __half* __restrict__ Ahi, const __half* __restrict__ Alo,
        const __half* __restrict__ Bh, const float* __restrict__ bias,
        __half* __restrict__ Chi, __half* __restrict__ Clo) {
    extern __shared__ char smem[];
    const uint32_t sb = smem_u32(smem);
    const int tid = threadIdx.x;
    const int wid = tid >> 5;
    const int lane = tid & 31;
    const int warp_m = wid & 3;
    const int warp_n = wid >> 2;
    const int m0 = blockIdx.y * 128;
    const int n0 = blockIdx.x * 128;
    const int M = NN, K = DIN, ldc = DHID;

    float acc[2][8][4];
    #pragma unroll
    for (int a = 0; a < 2; a++)
        #pragma unroll
        for (int b = 0; b < 8; b++)
            #pragma unroll
            for (int c = 0; c < 4; c++) acc[a][b][c] = 0.f;

    const int nchunks = K >> 5;

    auto load_chunk = [&](int ch) {
        const int k0 = ch << 5;
        const uint32_t stg = sb + (ch % NSTAGE) * STAGEB;
        #pragma unroll
        for (int it = 0; it < 2; it++) {
            int idx = tid + it * 256;
            int row = idx >> 2;
            int c = idx & 3;
            uint32_t soff = (uint32_t)(row * ROWB + c * 16);
            int gmr = m0 + row;
            bool okA = gmr < M;
            cp_async16(stg + SM_AHI + soff, Ahi + (size_t)gmr * K + k0 + c * 8, okA);
            cp_async16(stg + SM_ALO + soff, Alo + (size_t)gmr * K + k0 + c * 8, okA);
            int gnr = n0 + row;
            cp_async16(stg + SM_BHI + soff, Bh + (size_t)gnr * K + k0 + c * 8, true);
        }
        cp_commit();
    };

    load_chunk(0);
    if (nchunks > 1) load_chunk(1);

    for (int ch = 0; ch < nchunks; ch++) {
        if (ch + 1 < nchunks) cp_wait1(); else cp_wait0();
        __syncthreads();

        const uint32_t stg = sb + (ch % NSTAGE) * STAGEB;
        const uint32_t lrow = (uint32_t)(lane & 15);
        const uint32_t lchk = (uint32_t)(lane >> 4);

        #pragma unroll
        for (int ks = 0; ks < 2; ks++) {
            uint32_t a_hi[2][4], a_lo[2][4];
            #pragma unroll
            for (int mt = 0; mt < 2; mt++) {
                uint32_t r = (uint32_t)(warp_m * 32 + mt * 16) + lrow;
                uint32_t addr = stg + r * ROWB + lchk * 16 + ks * 32;
                ldsm_x4(a_hi[mt], addr + SM_AHI);
                ldsm_x4(a_lo[mt], addr + SM_ALO);
            }
            #pragma unroll
            for (int np = 0; np < 4; np++) {
                uint32_t bh[4];
                uint32_t r = (uint32_t)(warp_n * 64 + np * 16) + lrow;
                uint32_t addr = stg + r * ROWB + lchk * 16 + ks * 32;
                ldsm_x4(bh, addr + SM_BHI);
                uint32_t b0h[2] = {bh[0], bh[2]}, b1h[2] = {bh[1], bh[3]};
                #pragma unroll
                for (int mt = 0; mt < 2; mt++) {
                    hmma(acc[mt][2 * np],     a_hi[mt], b0h);
                    hmma(acc[mt][2 * np],     a_lo[mt], b0h);
                    hmma(acc[mt][2 * np + 1], a_hi[mt], b1h);
                    hmma(acc[mt][2 * np + 1], a_lo[mt], b1h);
                }
            }
        }
        // No trailing sync: with 3 stages, load(ch+2) writes stage (ch-1)%3
        // which every warp finished reading before passing the barrier above.
        if (ch + 2 < nchunks) load_chunk(ch + 2);
    }

    #pragma unroll
    for (int mt = 0; mt < 2; mt++) {
        int row = m0 + warp_m * 32 + mt * 16 + (lane >> 2);
        #pragma unroll
        for (int nt = 0; nt < 8; nt++) {
            int col = n0 + warp_n * 64 + nt * 8 + 2 * (lane & 3);
            float bx = bias[col], by = bias[col + 1];
            #pragma unroll
            for (int h = 0; h < 2; h++) {
                int r = row + h * 8;
                if (r >= M) continue;
                float v0 = acc[mt][nt][2 * h + 0] + bx;
                float v1 = acc[mt][nt][2 * h + 1] + by;
                v0 = v0 > 0.f ? v0 : 0.01f * v0;
                v1 = v1 > 0.f ? v1 : 0.01f * v1;
                __half h0 = __float2half_rn(v0);
                __half h1 = __float2half_rn(v1);
                __half l0 = __float2half_rn(v0 - __half2float(h0));
                __half l1 = __float2half_rn(v1 - __half2float(h1));
                size_t idx = (size_t)r * ldc + col;
                *reinterpret_cast<__half2*>(Chi + idx) = __halves2half2(h0, h1);
                *reinterpret_cast<__half2*>(Clo + idx) = __halves2half2(l0, l1);
            }
        }
    }
}

// ---------------------------------------------------------------------------
// 7) GEMM2: h2 = lrelu(hmid @ W2^T + b2) -> fp32 (+fused BN stats).
//    Persistent 512-thread CTAs (16 warps, 4m x 4n, warp tile 16x64),
//    M-tile 64, FULL N=256 per CTA (A read once), dynamic tile claim,
//    3-stage ring, 2 CTAs/SM.
// ---------------------------------------------------------------------------
#define G2_ASZ (64 * ROWB)                       // 5120 per A matrix
#define G2_BOFF (2 * G2_ASZ)                     // 10240
#define G2_STG (2 * G2_ASZ + 256 * ROWB)         // 30720
#define G2_SMEM (3 * G2_STG)                     // 92160
#define G2_NT ((NN + 63) / 64)                   // 782

__global__ void __launch_bounds__(512, 2)
k_gemm2(const __half* __restrict__ Ahi, const __half* __restrict__ Alo,
        const __half* __restrict__ Bh, const float* __restrict__ bias,
        float* __restrict__ Cf) {
    extern __shared__ char smem[];
    __shared__ int s_tile;
    const uint32_t sb = smem_u32(smem);
    const int tid = threadIdx.x;
    const int wid = tid >> 5;
    const int lane = tid & 31;
    const int warp_m = wid & 3;      // 4 m-warps of 16 rows
    const int warp_n = wid >> 2;     // 4 n-warps of 64 cols
    const int M = NN, K = DHID, ldc = DOUT;
    const int nchunks = K >> 5;      // 16
    float* sarr = reinterpret_cast<float*>(smem);      // reused post-mainloop
    float* qarr = sarr + DOUT;

    while (true) {
        if (tid == 0) s_tile = atomicAdd(&g_tile2, 1);
        __syncthreads();
        const int tile = s_tile;
        if (tile >= G2_NT) break;
        const int m0 = tile * 64;

        float acc[8][4];
        #pragma unroll
        for (int b = 0; b < 8; b++)
            #pragma unroll
            for (int c = 0; c < 4; c++) acc[b][c] = 0.f;

        auto load_chunk = [&](int ch) {
            const int k0 = ch << 5;
            const uint32_t stg = sb + (ch % 3) * G2_STG;
            if (tid < 256) {             // A: 64 rows x 4 chunks, hi+lo
                int row = tid >> 2;
                int c = tid & 3;
                uint32_t soff = (uint32_t)(row * ROWB + c * 16);
                int gmr = m0 + row;
                bool ok = gmr < M;
                cp_async16(stg + soff, Ahi + (size_t)gmr * K + k0 + c * 8, ok);
                cp_async16(stg + G2_ASZ + soff, Alo + (size_t)gmr * K + k0 + c * 8, ok);
            }
            #pragma unroll
            for (int it = 0; it < 2; it++) {  // B: 256 rows x 4 chunks
                int idx = tid + it * 512;
                int row = idx >> 2;
                int c = idx & 3;
                uint32_t soff = (uint32_t)(row * ROWB + c * 16);
                cp_async16(stg + G2_BOFF + soff, Bh + (size_t)row * K + k0 + c * 8, true);
            }
            cp_commit();
        };

        load_chunk(0);
        load_chunk(1);

        for (int ch = 0; ch < nchunks; ch++) {
            if (ch + 1 < nchunks) cp_wait1(); else cp_wait0();
            __syncthreads();

            const uint32_t stg = sb + (ch % 3) * G2_STG;
            const uint32_t lrow = (uint32_t)(lane & 15);
            const uint32_t lchk = (uint32_t)(lane >> 4);

            #pragma unroll
            for (int ks = 0; ks < 2; ks++) {
                uint32_t a_hi[4], a_lo[4];
                {
                    uint32_t r = (uint32_t)(warp_m * 16) + lrow;
                    uint32_t addr = stg + r * ROWB + lchk * 16 + ks * 32;
                    ldsm_x4(a_hi, addr);
                    ldsm_x4(a_lo, addr + G2_ASZ);
                }
                #pragma unroll
                for (int np = 0; np < 4; np++) {
                    uint32_t bh[4];
                    uint32_t r = (uint32_t)(warp_n * 64 + np * 16) + lrow;
                    uint32_t addr = stg + G2_BOFF + r * ROWB + lchk * 16 + ks * 32;
                    ldsm_x4(bh, addr);
                    uint32_t b0h[2] = {bh[0], bh[2]}, b1h[2] = {bh[1], bh[3]};
                    hmma(acc[2 * np],     a_hi, b0h);
                    hmma(acc[2 * np],     a_lo, b0h);
                    hmma(acc[2 * np + 1], a_hi, b1h);
                    hmma(acc[2 * np + 1], a_lo, b1h);
                }
            }
            if (ch + 2 < nchunks) load_chunk(ch + 2);
        }

        // Epilogue: bias + lrelu + store + BN stats (per-nt immediate reduce)
        __syncthreads();                 // stages free; reuse smem for stats
        if (tid < DOUT) { sarr[tid] = 0.f; qarr[tid] = 0.f; }
        __syncthreads();

        int row = m0 + warp_m * 16 + (lane >> 2);
        #pragma unroll
        for (int nt = 0; nt < 8; nt++) {
            int col = warp_n * 64 + nt * 8 + 2 * (lane & 3);
            float bx = bias[col], by = bias[col + 1];
            float s0 = 0.f, s1 = 0.f, q0 = 0.f, q1 = 0.f;
            #pragma unroll
            for (int h = 0; h < 2; h++) {
                int r = row + h * 8;
                if (r >= M) continue;
                float v0 = acc[nt][2 * h + 0] + bx;
                float v1 = acc[nt][2 * h + 1] + by;
                v0 = v0 > 0.f ? v0 : 0.01f * v0;
                v1 = v1 > 0.f ? v1 : 0.01f * v1;
                *reinterpret_cast<float2*>(Cf + (size_t)r * ldc + col) =
                    make_float2(v0, v1);
                s0 += v0; q0 += v0 * v0;
                s1 += v1; q1 += v1 * v1;
            }
            #pragma unroll
            for (int o = 4; o < 32; o <<= 1) {
                s0 += __shfl_xor_sync(0xffffffffu, s0, o);
                s1 += __shfl_xor_sync(0xffffffffu, s1, o);
                q0 += __shfl_xor_sync(0xffffffffu, q0, o);
                q1 += __shfl_xor_sync(0xffffffffu, q1, o);
            }
            if (lane < 4) {
                int c = warp_n * 64 + nt * 8 + 2 * lane;
                atomicAdd(&sarr[c], s0);
                atomicAdd(&sarr[c + 1], s1);
                atomicAdd(&qarr[c], q0);
                atomicAdd(&qarr[c + 1], q1);
            }
        }
        __syncthreads();
        if (tid < DOUT) {
            atomicAdd(&g_sum[tid], sarr[tid]);
            atomicAdd(&g_sumsq[tid], qarr[tid]);
        }
        __syncthreads();                 // protect sarr + s_tile before reuse
    }
}

// ---------------------------------------------------------------------------
// 8) BN finalize + normalize
// ---------------------------------------------------------------------------
__global__ void k_bn_finalize(const float* __restrict__ gamma,
                              const float* __restrict__ beta) {
    int c = threadIdx.x;
    float invn = 1.0f / (float)NN;
    float mean = g_sum[c] * invn;
    float var = g_sumsq[c] * invn - mean * mean;
    float rstd = rsqrtf(var + 1e-5f);
    float sc = gamma[c] * rstd;
    g_scale[c] = sc;
    g_shift[c] = beta[c] - mean * sc;
}

__global__ void k_normalize(float* __restrict__ out) {
    int i = blockIdx.x * blockDim.x + threadIdx.x;
    const int n4 = NN * DOUT / 4;
    if (i >= n4) return;
    int c4 = i & (DOUT / 4 - 1);
    float4 v = reinterpret_cast<const float4*>(g_h2)[i];
    float4 sc = reinterpret_cast<const float4*>(g_scale)[c4];
    float4 sh = reinterpret_cast<const float4*>(g_shift)[c4];
    v.x = v.x * sc.x + sh.x;
    v.y = v.y * sc.y + sh.y;
    v.z = v.z * sc.z + sh.z;
    v.w = v.w * sc.w + sh.w;
    reinterpret_cast<float4*>(out)[i] = v;
}

// ---------------------------------------------------------------------------
extern "C" void kernel_launch(void* const* d_in, const int* in_sizes, int n_in,
                              void* d_out, int out_size) {
    const float* x     = (const float*)d_in[0];
    const int*   ei    = (const int*)d_in[1];
    const float* W1    = (const float*)d_in[2];
    const float* b1    = (const float*)d_in[3];
    const float* W2    = (const float*)d_in[4];
    const float* b2    = (const float*)d_in[5];
    const float* gamma = (const float*)d_in[6];
    const float* beta  = (const float*)d_in[7];
    float* out = (float*)d_out;

    __half *xhi, *xlo, *mhi, *mlo, *w1hi, *w2hi;
    float* h2;
    cudaGetSymbolAddress((void**)&xhi, g_xhi);
    cudaGetSymbolAddress((void**)&xlo, g_xlo);
    cudaGetSymbolAddress((void**)&mhi, g_mhi);
    cudaGetSymbolAddress((void**)&mlo, g_mlo);
    cudaGetSymbolAddress((void**)&w1hi, g_w1hi);
    cudaGetSymbolAddress((void**)&w2hi, g_w2hi);
    cudaGetSymbolAddress((void**)&h2, g_h2);

    cudaFuncSetAttribute(k_gemm1,
                         cudaFuncAttributeMaxDynamicSharedMemorySize, G1_SMEM);
    cudaFuncSetAttribute(k_gemm2,
                         cudaFuncAttributeMaxDynamicSharedMemorySize, G2_SMEM);

    // CSR build + aggregate (+fused fp16 split)
    k_zero<<<(NN + 255) / 256, 256>>>();
    k_hist<<<(NE + 255) / 256, 256>>>(ei);
    k_scan<<<1, 1024>>>();
    k_bucket<<<(NE + 255) / 256, 256>>>(ei);
    k_agg<<<(NN * 32 + 255) / 256, 256>>>(x);

    // weight prep
    k_prep_w<<<(DIN * DHID + 255) / 256, 256>>>(W1, w1hi, DIN, DHID);
    k_prep_w<<<(DHID * DOUT + 255) / 256, 256>>>(W2, w2hi, DHID, DOUT);

    // GEMM1: [50000x128]@[128x512] -> fp16 hi/lo
    {
        dim3 grid(DHID / 128, (NN + 127) / 128);
        k_gemm1<<<grid, 256, G1_SMEM>>>(xhi, xlo, w1hi, b1, mhi, mlo);
    }
    // GEMM2: [50000x512]@[512x256] -> fp32 (+fused BN stats), persistent
    k_gemm2<<<296, 512, G2_SMEM>>>(mhi, mlo, w2hi, b2, h2);

    // BN
    k_bn_finalize<<<1, DOUT>>>(gamma, beta);
    k_normalize<<<(NN * DOUT / 4 + 255) / 256, 256>>>(out);
}

// round 9
// speedup vs baseline: 1.0386x; 1.0386x over previous
#include <cuda_runtime.h>
#include <cuda_fp16.h>
#include <cstdint>
#include <cstddef>

#define NN 50000
#define NE 800000
#define DIN 128
#define DHID 512
#define DOUT 256

// ---------------------------------------------------------------------------
// Scratch (device globals — no runtime allocation)
// ---------------------------------------------------------------------------
__device__ __half g_xhi[(size_t)NN * DIN];       // (x+agg) split hi
__device__ __half g_xlo[(size_t)NN * DIN];       // (x+agg) residual
__device__ __half g_mhi[(size_t)NN * DHID];      // hmid hi
__device__ __half g_mlo[(size_t)NN * DHID];      // hmid residual
__device__ float g_h2[(size_t)NN * DOUT];        // after layer2+act (fp32)
__device__ __half g_w1hi[(size_t)DHID * DIN];    // W1^T [N][K] fp16
__device__ __half g_w2hi[(size_t)DOUT * DHID];   // W2^T [N][K] fp16
__device__ float g_sum[DOUT];
__device__ float g_sumsq[DOUT];
// CSR build
__device__ int g_deg[NN];
__device__ int g_off[NN + 1];
__device__ int g_cur[NN];
__device__ int g_srcs[NE];

// ---------------------------------------------------------------------------
// PTX helpers
// ---------------------------------------------------------------------------
__device__ __forceinline__ uint32_t smem_u32(const void* p) {
    uint32_t a;
    asm("{ .reg .u64 t; cvta.to.shared.u64 t, %1; cvt.u32.u64 %0, t; }"
        : "=r"(a) : "l"(p));
    return a;
}
__device__ __forceinline__ void cp_async16(uint32_t dst, const void* src, bool pred) {
    int sz = pred ? 16 : 0;
    asm volatile("cp.async.cg.shared.global [%0], [%1], 16, %2;"
                 :: "r"(dst), "l"(src), "r"(sz));
}
__device__ __forceinline__ void cp_commit() {
    asm volatile("cp.async.commit_group;" ::: "memory");
}
__device__ __forceinline__ void cp_wait0() {
    asm volatile("cp.async.wait_group 0;" ::: "memory");
}
__device__ __forceinline__ void cp_wait1() {
    asm volatile("cp.async.wait_group 1;" ::: "memory");
}
__device__ __forceinline__ void ldsm_x4(uint32_t* r, uint32_t addr) {
    asm volatile("ldmatrix.sync.aligned.m8n8.x4.shared.b16 {%0,%1,%2,%3}, [%4];"
                 : "=r"(r[0]), "=r"(r[1]), "=r"(r[2]), "=r"(r[3]) : "r"(addr));
}
__device__ __forceinline__ void hmma(float* c, const uint32_t* a, const uint32_t* b) {
    asm volatile(
        "mma.sync.aligned.m16n8k16.row.col.f32.f16.f16.f32 "
        "{%0,%1,%2,%3}, {%4,%5,%6,%7}, {%8,%9}, {%0,%1,%2,%3};"
        : "+f"(c[0]), "+f"(c[1]), "+f"(c[2]), "+f"(c[3])
        : "r"(a[0]), "r"(a[1]), "r"(a[2]), "r"(a[3]), "r"(b[0]), "r"(b[1]));
}

// ---------------------------------------------------------------------------
// 0) zero: degree counters + BN accumulators
// ---------------------------------------------------------------------------
__global__ void k_zero() {
    int i = blockIdx.x * blockDim.x + threadIdx.x;
    if (i < NN) g_deg[i] = 0;
    if (i < DOUT) { g_sum[i] = 0.f; g_sumsq[i] = 0.f; }
}

// ---------------------------------------------------------------------------
// 1) histogram of dst degrees
// ---------------------------------------------------------------------------
__global__ void k_hist(const int* __restrict__ ei) {
    int e = blockIdx.x * blockDim.x + threadIdx.x;
    if (e < NE) atomicAdd(&g_deg[ei[NE + e]], 1);
}

// ---------------------------------------------------------------------------
// 2) exclusive scan over degrees (single block)
// ---------------------------------------------------------------------------
__global__ void __launch_bounds__(1024) k_scan() {
    __shared__ int bs[1024];
    const int t = threadIdx.x;
    const int SEG = (NN + 1023) / 1024;
    int start = t * SEG;
    int stop = start + SEG < NN ? start + SEG : NN;
    int s = 0;
    for (int i = start; i < stop; i++) s += g_deg[i];
    bs[t] = s;
    __syncthreads();
    for (int d = 1; d < 1024; d <<= 1) {
        int u = (t >= d) ? bs[t - d] : 0;
        __syncthreads();
        if (t >= d) bs[t] += u;
        __syncthreads();
    }
    int run = bs[t] - s;
    for (int i = start; i < stop; i++) {
        g_off[i] = run;
        g_cur[i] = run;
        run += g_deg[i];
    }
    if (t == 1023) g_off[NN] = run;
}

// ---------------------------------------------------------------------------
// 3) bucket edges by dst
// ---------------------------------------------------------------------------
__global__ void k_bucket(const int* __restrict__ ei) {
    int e = blockIdx.x * blockDim.x + threadIdx.x;
    if (e >= NE) return;
    int dst = ei[NE + e];
    int pos = atomicAdd(&g_cur[dst], 1);
    g_srcs[pos] = ei[e];
}

// ---------------------------------------------------------------------------
// 4) aggregate: one warp per node; split hi/lo fp16
// ---------------------------------------------------------------------------
__global__ void __launch_bounds__(256) k_agg(const float* __restrict__ x) {
    int w = (blockIdx.x * blockDim.x + threadIdx.x) >> 5;
    if (w >= NN) return;
    int lane = threadIdx.x & 31;

    float4 acc = reinterpret_cast<const float4*>(x + (size_t)w * DIN)[lane];
    int beg = g_off[w], end = g_off[w + 1];
    for (int base = beg; base < end; base += 32) {
        int n = end - base;
        if (n > 32) n = 32;
        int s = (lane < n) ? g_srcs[base + lane] : 0;
        #pragma unroll 4
        for (int j = 0; j < n; j++) {
            int src = __shfl_sync(0xffffffffu, s, j);
            float4 v = reinterpret_cast<const float4*>(x + (size_t)src * DIN)[lane];
            acc.x += v.x; acc.y += v.y; acc.z += v.z; acc.w += v.w;
        }
    }
    __half hx = __float2half_rn(acc.x), hy = __float2half_rn(acc.y);
    __half hz = __float2half_rn(acc.z), hw = __float2half_rn(acc.w);
    __half lx = __float2half_rn(acc.x - __half2float(hx));
    __half ly = __float2half_rn(acc.y - __half2float(hy));
    __half lz = __float2half_rn(acc.z - __half2float(hz));
    __half lw = __float2half_rn(acc.w - __half2float(hw));
    size_t idx = (size_t)w * DIN + lane * 4;
    __half2* phi = reinterpret_cast<__half2*>(g_xhi + idx);
    __half2* plo = reinterpret_cast<__half2*>(g_xlo + idx);
    phi[0] = __halves2half2(hx, hy);
    phi[1] = __halves2half2(hz, hw);
    plo[0] = __halves2half2(lx, ly);
    plo[1] = __halves2half2(lz, lw);
}

// ---------------------------------------------------------------------------
// 5) W [K,N] -> W^T [N,K] fp16
// ---------------------------------------------------------------------------
__global__ void k_prep_w(const float* __restrict__ W, __half* __restrict__ hi,
                         int K, int N) {
    int i = blockIdx.x * blockDim.x + threadIdx.x;
    if (i >= K * N) return;
    int n = i / K, k = i % K;
    hi[i] = __float2half_rn(W[(size_t)k * N + n]);
}

// ---------------------------------------------------------------------------
// 6) GEMM1 single-shot: hmid = lrelu(A @ W1^T + b1) -> fp16 hi/lo.
//    K=128 loaded entirely in one cp.async wave (no K-loop, no ring).
//    CTA 128x128, 8 warps (4m x 2n), 2 CTAs/SM.
//    Rows padded 256B->272B: stride = 68 words = 4 mod 32 -> conflict-free ldsm.
// ---------------------------------------------------------------------------
#define A1_ROWB 272
#define A1_SZ (128 * A1_ROWB)        // 34816
#define G1_AHI 0
#define G1_ALO A1_SZ
#define G1_B   (2 * A1_SZ)
#define G1_SMEM (3 * A1_SZ)          // 104448 -> 2 CTAs/SM (208896 < 228KB)

__global__ void __launch_bounds__(256, 2)
k_gemm1(const __half* __restrict__ Ahi, const __half* __restrict__ Alo,
        const __half* __restrict__ Bh, const float* __restrict__ bias,
        __half* __restrict__ Chi, __half* __restrict__ Clo) {
    extern __shared__ char smem[];
    const uint32_t sb = smem_u32(smem);
    const int tid = threadIdx.x;
    const int wid = tid >> 5;
    const int lane = tid & 31;
    const int warp_m = wid & 3;
    const int warp_n = wid >> 2;
    const int m0 = blockIdx.y * 128;
    const int n0 = blockIdx.x * 128;
    const int M = NN, K = DIN, ldc = DHID;

    // Load the whole 128x128 A (hi+lo) and B tile in one wave.
    #pragma unroll
    for (int it = 0; it < 8; it++) {
        int idx = tid + it * 256;            // 0..2047
        int row = idx >> 4;                  // 0..127
        int c = idx & 15;                    // 16B chunk within 256B row
        uint32_t soff = (uint32_t)(row * A1_ROWB + c * 16);
        int gmr = m0 + row;
        bool ok = gmr < M;
        cp_async16(sb + G1_AHI + soff, Ahi + (size_t)gmr * K + c * 8, ok);
        cp_async16(sb + G1_ALO + soff, Alo + (size_t)gmr * K + c * 8, ok);
        int gnr = n0 + row;
        cp_async16(sb + G1_B + soff, Bh + (size_t)gnr * K + c * 8, true);
    }
    cp_commit();
    cp_wait0();
    __syncthreads();

    float acc[2][8][4];
    #pragma unroll
    for (int a = 0; a < 2; a++)
        #pragma unroll
        for (int b = 0; b < 8; b++)
            #pragma unroll
            for (int c = 0; c < 4; c++) acc[a][b][c] = 0.f;

    const uint32_t lrow = (uint32_t)(lane & 15);
    const uint32_t lchk = (uint32_t)(lane >> 4);

    #pragma unroll
    for (int ks = 0; ks < 8; ks++) {
        uint32_t a_hi[2][4], a_lo[2][4];
        #pragma unroll
        for (int mt = 0; mt < 2; mt++) {
            uint32_t r = (uint32_t)(warp_m * 32 + mt * 16) + lrow;
            uint32_t addr = sb + r * A1_ROWB + lchk * 16 + ks * 32;
            ldsm_x4(a_hi[mt], addr + G1_AHI);
            ldsm_x4(a_lo[mt], addr + G1_ALO);
        }
        #pragma unroll
        for (int np = 0; np < 4; np++) {
            uint32_t bh[4];
            uint32_t r = (uint32_t)(warp_n * 64 + np * 16) + lrow;
            uint32_t addr = sb + G1_B + r * A1_ROWB + lchk * 16 + ks * 32;
            ldsm_x4(bh, addr);
            uint32_t b0h[2] = {bh[0], bh[2]}, b1h[2] = {bh[1], bh[3]};
            #pragma unroll
            for (int mt = 0; mt < 2; mt++) {
                hmma(acc[mt][2 * np],     a_hi[mt], b0h);
                hmma(acc[mt][2 * np],     a_lo[mt], b0h);
                hmma(acc[mt][2 * np + 1], a_hi[mt], b1h);
                hmma(acc[mt][2 * np + 1], a_lo[mt], b1h);
            }
        }
    }

    #pragma unroll
    for (int mt = 0; mt < 2; mt++) {
        int row = m0 + warp_m * 32 + mt * 16 + (lane >> 2);
        #pragma unroll
        for (int nt = 0; nt < 8; nt++) {
            int col = n0 + warp_n * 64 + nt * 8 + 2 * (lane & 3);
            float bx = bias[col], by = bias[col + 1];
            #pragma unroll
            for (int h = 0; h < 2; h++) {
                int r = row + h * 8;
                if (r >= M) continue;
                float v0 = acc[mt][nt][2 * h + 0] + bx;
                float v1 = acc[mt][nt][2 * h + 1] + by;
                v0 = v0 > 0.f ? v0 : 0.01f * v0;
                v1 = v1 > 0.f ? v1 : 0.01f * v1;
                __half h0 = __float2half_rn(v0);
                __half h1 = __float2half_rn(v1);
                __half l0 = __float2half_rn(v0 - __half2float(h0));
                __half l1 = __float2half_rn(v1 - __half2float(h1));
                size_t idx = (size_t)r * ldc + col;
                *reinterpret_cast<__half2*>(Chi + idx) = __halves2half2(h0, h1);
                *reinterpret_cast<__half2*>(Clo + idx) = __halves2half2(l0, l1);
            }
        }
    }
}

// ---------------------------------------------------------------------------
// 7) GEMM2 (round-7 design): h2 = lrelu(hmid @ W2^T + b2) -> fp32 + BN stats.
//    CTA 128x128, BK=32, 8 warps (4m x 2n), 3-stage ring, 2 CTAs/SM.
// ---------------------------------------------------------------------------
#define ROWB 80
#define MATB (128 * ROWB)
#define STAGEB (3 * MATB)
#define SM_AHI 0
#define SM_ALO MATB
#define SM_BHI (2 * MATB)
#define G2_SMEM (3 * STAGEB)         // 92160

__global__ void __launch_bounds__(256, 2)
k_gemm2(const __half* __restrict__ Ahi, const __half* __restrict__ Alo,
        const __half* __restrict__ Bh, const float* __restrict__ bias,
        float* __restrict__ Cf) {
    extern __shared__ char smem[];
    const uint32_t sb = smem_u32(smem);
    const int tid = threadIdx.x;
    const int wid = tid >> 5;
    const int lane = tid & 31;
    const int warp_m = wid & 3;
    const int warp_n = wid >> 2;
    const int m0 = blockIdx.y * 128;
    const int n0 = blockIdx.x * 128;
    const int M = NN, K = DHID, ldc = DOUT;

    float acc[2][8][4];
    #pragma unroll
    for (int a = 0; a < 2; a++)
        #pragma unroll
        for (int b = 0; b < 8; b++)
            #pragma unroll
            for (int c = 0; c < 4; c++) acc[a][b][c] = 0.f;

    const int nchunks = K >> 5;

    auto load_chunk = [&](int ch) {
        const int k0 = ch << 5;
        const uint32_t stg = sb + (ch % 3) * STAGEB;
        #pragma unroll
        for (int it = 0; it < 2; it++) {
            int idx = tid + it * 256;
            int row = idx >> 2;
            int c = idx & 3;
            uint32_t soff = (uint32_t)(row * ROWB + c * 16);
            int gmr = m0 + row;
            bool okA = gmr < M;
            cp_async16(stg + SM_AHI + soff, Ahi + (size_t)gmr * K + k0 + c * 8, okA);
            cp_async16(stg + SM_ALO + soff, Alo + (size_t)gmr * K + k0 + c * 8, okA);
            int gnr = n0 + row;
            cp_async16(stg + SM_BHI + soff, Bh + (size_t)gnr * K + k0 + c * 8, true);
        }
        cp_commit();
    };

    load_chunk(0);
    load_chunk(1);

    for (int ch = 0; ch < nchunks; ch++) {
        if (ch + 1 < nchunks) cp_wait1(); else cp_wait0();
        __syncthreads();

        const uint32_t stg = sb + (ch % 3) * STAGEB;
        const uint32_t lrow = (uint32_t)(lane & 15);
        const uint32_t lchk = (uint32_t)(lane >> 4);

        #pragma unroll
        for (int ks = 0; ks < 2; ks++) {
            uint32_t a_hi[2][4], a_lo[2][4];
            #pragma unroll
            for (int mt = 0; mt < 2; mt++) {
                uint32_t r = (uint32_t)(warp_m * 32 + mt * 16) + lrow;
                uint32_t addr = stg + r * ROWB + lchk * 16 + ks * 32;
                ldsm_x4(a_hi[mt], addr + SM_AHI);
                ldsm_x4(a_lo[mt], addr + SM_ALO);
            }
            #pragma unroll
            for (int np = 0; np < 4; np++) {
                uint32_t bh[4];
                uint32_t r = (uint32_t)(warp_n * 64 + np * 16) + lrow;
                uint32_t addr = stg + r * ROWB + lchk * 16 + ks * 32;
                ldsm_x4(bh, addr + SM_BHI);
                uint32_t b0h[2] = {bh[0], bh[2]}, b1h[2] = {bh[1], bh[3]};
                #pragma unroll
                for (int mt = 0; mt < 2; mt++) {
                    hmma(acc[mt][2 * np],     a_hi[mt], b0h);
                    hmma(acc[mt][2 * np],     a_lo[mt], b0h);
                    hmma(acc[mt][2 * np + 1], a_hi[mt], b1h);
                    hmma(acc[mt][2 * np + 1], a_lo[mt], b1h);
                }
            }
        }
        if (ch + 2 < nchunks) load_chunk(ch + 2);
    }

    // Epilogue: bias + lrelu + store + BN stats
    float scol[8][2];
    float qcol[8][2];
    #pragma unroll
    for (int nt = 0; nt < 8; nt++) {
        scol[nt][0] = scol[nt][1] = 0.f;
        qcol[nt][0] = qcol[nt][1] = 0.f;
    }

    #pragma unroll
    for (int mt = 0; mt < 2; mt++) {
        int row = m0 + warp_m * 32 + mt * 16 + (lane >> 2);
        #pragma unroll
        for (int nt = 0; nt < 8; nt++) {
            int col = n0 + warp_n * 64 + nt * 8 + 2 * (lane & 3);
            float bx = bias[col], by = bias[col + 1];
            #pragma unroll
            for (int h = 0; h < 2; h++) {
                int r = row + h * 8;
                if (r >= M) continue;
                float v0 = acc[mt][nt][2 * h + 0] + bx;
                float v1 = acc[mt][nt][2 * h + 1] + by;
                v0 = v0 > 0.f ? v0 : 0.01f * v0;
                v1 = v1 > 0.f ? v1 : 0.01f * v1;
                size_t idx = (size_t)r * ldc + col;
                *reinterpret_cast<float2*>(Cf + idx) = make_float2(v0, v1);
                scol[nt][0] += v0; qcol[nt][0] += v0 * v0;
                scol[nt][1] += v1; qcol[nt][1] += v1 * v1;
            }
        }
    }

    {
        float* sarr = reinterpret_cast<float*>(smem);
        float* qarr = sarr + 128;
        __syncthreads();
        if (tid < 128) { sarr[tid] = 0.f; qarr[tid] = 0.f; }
        __syncthreads();
        #pragma unroll
        for (int nt = 0; nt < 8; nt++) {
            float s0 = scol[nt][0], s1 = scol[nt][1];
            float q0 = qcol[nt][0], q1 = qcol[nt][1];
            #pragma unroll
            for (int o = 4; o < 32; o <<= 1) {
                s0 += __shfl_xor_sync(0xffffffffu, s0, o);
                s1 += __shfl_xor_sync(0xffffffffu, s1, o);
                q0 += __shfl_xor_sync(0xffffffffu, q0, o);
                q1 += __shfl_xor_sync(0xffffffffu, q1, o);
            }
            if (lane < 4) {
                int c = warp_n * 64 + nt * 8 + 2 * lane;
                atomicAdd(&sarr[c], s0);
                atomicAdd(&sarr[c + 1], s1);
                atomicAdd(&qarr[c], q0);
                atomicAdd(&qarr[c + 1], q1);
            }
        }
        __syncthreads();
        if (tid < 128) {
            atomicAdd(&g_sum[n0 + tid], sarr[tid]);
            atomicAdd(&g_sumsq[n0 + tid], qarr[tid]);
        }
    }
}

// ---------------------------------------------------------------------------
// 8) normalize with inline BN finalize (per-block scale/shift from g_sum)
// ---------------------------------------------------------------------------
__global__ void __launch_bounds__(256) k_normalize(float* __restrict__ out,
                                                   const float* __restrict__ gamma,
                                                   const float* __restrict__ beta) {
    __shared__ float4 s_sc[DOUT / 4];
    __shared__ float4 s_sh[DOUT / 4];
    const int tid = threadIdx.x;
    if (tid < DOUT / 4) {
        const float invn = 1.0f / (float)NN;
        float4 sc, sh;
        #pragma unroll
        for (int k = 0; k < 4; k++) {
            int c = tid * 4 + k;
            float mean = g_sum[c] * invn;
            float var = g_sumsq[c] * invn - mean * mean;
            float rstd = rsqrtf(var + 1e-5f);
            float s = gamma[c] * rstd;
            (&sc.x)[k] = s;
            (&sh.x)[k] = beta[c] - mean * s;
        }
        s_sc[tid] = sc;
        s_sh[tid] = sh;
    }
    __syncthreads();

    int i = blockIdx.x * blockDim.x + tid;
    const int n4 = NN * DOUT / 4;
    if (i >= n4) return;
    int c4 = i & (DOUT / 4 - 1);
    float4 v = reinterpret_cast<const float4*>(g_h2)[i];
    float4 sc = s_sc[c4];
    float4 sh = s_sh[c4];
    v.x = v.x * sc.x + sh.x;
    v.y = v.y * sc.y + sh.y;
    v.z = v.z * sc.z + sh.z;
    v.w = v.w * sc.w + sh.w;
    reinterpret_cast<float4*>(out)[i] = v;
}

// ---------------------------------------------------------------------------
extern "C" void kernel_launch(void* const* d_in, const int* in_sizes, int n_in,
                              void* d_out, int out_size) {
    const float* x     = (const float*)d_in[0];
    const int*   ei    = (const int*)d_in[1];
    const float* W1    = (const float*)d_in[2];
    const float* b1    = (const float*)d_in[3];
    const float* W2    = (const float*)d_in[4];
    const float* b2    = (const float*)d_in[5];
    const float* gamma = (const float*)d_in[6];
    const float* beta  = (const float*)d_in[7];
    float* out = (float*)d_out;

    __half *xhi, *xlo, *mhi, *mlo, *w1hi, *w2hi;
    float* h2;
    cudaGetSymbolAddress((void**)&xhi, g_xhi);
    cudaGetSymbolAddress((void**)&xlo, g_xlo);
    cudaGetSymbolAddress((void**)&mhi, g_mhi);
    cudaGetSymbolAddress((void**)&mlo, g_mlo);
    cudaGetSymbolAddress((void**)&w1hi, g_w1hi);
    cudaGetSymbolAddress((void**)&w2hi, g_w2hi);
    cudaGetSymbolAddress((void**)&h2, g_h2);

    cudaFuncSetAttribute(k_gemm1,
                         cudaFuncAttributeMaxDynamicSharedMemorySize, G1_SMEM);
    cudaFuncSetAttribute(k_gemm2,
                         cudaFuncAttributeMaxDynamicSharedMemorySize, G2_SMEM);

    // CSR build + aggregate (+fused fp16 split)
    k_zero<<<(NN + 255) / 256, 256>>>();
    k_hist<<<(NE + 255) / 256, 256>>>(ei);
    k_scan<<<1, 1024>>>();
    k_bucket<<<(NE + 255) / 256, 256>>>(ei);
    k_agg<<<(NN * 32 + 255) / 256, 256>>>(x);

    // weight prep
    k_prep_w<<<(DIN * DHID + 255) / 256, 256>>>(W1, w1hi, DIN, DHID);
    k_prep_w<<<(DHID * DOUT + 255) / 256, 256>>>(W2, w2hi, DHID, DOUT);

    // GEMM1: [50000x128]@[128x512] -> fp16 hi/lo (single-shot K)
    {
        dim3 grid(DHID / 128, (NN + 127) / 128);
        k_gemm1<<<grid, 256, G1_SMEM>>>(xhi, xlo, w1hi, b1, mhi, mlo);
    }
    // GEMM2: [50000x512]@[512x256] -> fp32 (+fused BN stats)
    {
        dim3 grid(DOUT / 128, (NN + 127) / 128);
        k_gemm2<<<grid, 256, G2_SMEM>>>(mhi, mlo, w2hi, b2, h2);
    }
    // normalize (inline BN finalize)
    k_normalize<<<(NN * DOUT / 4 + 255) / 256, 256>>>(out, gamma, beta);
}

// round 10
// speedup vs baseline: 1.3304x; 1.2809x over previous
#include <cuda_runtime.h>
#include <cuda_fp16.h>
#include <cstdint>
#include <cstddef>

#define NN 50000
#define NE 800000
#define DIN 128
#define DHID 512
#define DOUT 256

// ---------------------------------------------------------------------------
// Scratch (device globals — no runtime allocation)
// ---------------------------------------------------------------------------
__device__ __half g_xhi[(size_t)NN * DIN];       // (x+agg) fp16
__device__ __half g_mhi[(size_t)NN * DHID];      // hmid fp16
__device__ float g_h2[(size_t)NN * DOUT];        // after layer2+act (fp32)
__device__ __half g_w1hi[(size_t)DHID * DIN];    // W1^T [N][K] fp16
__device__ __half g_w2hi[(size_t)DOUT * DHID];   // W2^T [N][K] fp16
__device__ float g_sum[DOUT];
__device__ float g_sumsq[DOUT];
// CSR build
__device__ int g_deg[NN];
__device__ int g_off[NN + 1];
__device__ int g_cur[NN];
__device__ int g_srcs[NE];

// ---------------------------------------------------------------------------
// PTX helpers
// ---------------------------------------------------------------------------
__device__ __forceinline__ uint32_t smem_u32(const void* p) {
    uint32_t a;
    asm("{ .reg .u64 t; cvta.to.shared.u64 t, %1; cvt.u32.u64 %0, t; }"
        : "=r"(a) : "l"(p));
    return a;
}
__device__ __forceinline__ void cp_async16(uint32_t dst, const void* src, bool pred) {
    int sz = pred ? 16 : 0;
    asm volatile("cp.async.cg.shared.global [%0], [%1], 16, %2;"
                 :: "r"(dst), "l"(src), "r"(sz));
}
__device__ __forceinline__ void cp_commit() {
    asm volatile("cp.async.commit_group;" ::: "memory");
}
__device__ __forceinline__ void cp_wait0() {
    asm volatile("cp.async.wait_group 0;" ::: "memory");
}
__device__ __forceinline__ void cp_wait1() {
    asm volatile("cp.async.wait_group 1;" ::: "memory");
}
__device__ __forceinline__ void ldsm_x4(uint32_t* r, uint32_t addr) {
    asm volatile("ldmatrix.sync.aligned.m8n8.x4.shared.b16 {%0,%1,%2,%3}, [%4];"
                 : "=r"(r[0]), "=r"(r[1]), "=r"(r[2]), "=r"(r[3]) : "r"(addr));
}
__device__ __forceinline__ void hmma(float* c, const uint32_t* a, const uint32_t* b) {
    asm volatile(
        "mma.sync.aligned.m16n8k16.row.col.f32.f16.f16.f32 "
        "{%0,%1,%2,%3}, {%4,%5,%6,%7}, {%8,%9}, {%0,%1,%2,%3};"
        : "+f"(c[0]), "+f"(c[1]), "+f"(c[2]), "+f"(c[3])
        : "r"(a[0]), "r"(a[1]), "r"(a[2]), "r"(a[3]), "r"(b[0]), "r"(b[1]));
}

// ---------------------------------------------------------------------------
// 0) zero: degree counters + BN accumulators
// ---------------------------------------------------------------------------
__global__ void k_zero() {
    int i = blockIdx.x * blockDim.x + threadIdx.x;
    if (i < NN) g_deg[i] = 0;
    if (i < DOUT) { g_sum[i] = 0.f; g_sumsq[i] = 0.f; }
}

// ---------------------------------------------------------------------------
// 1) histogram of dst degrees
// ---------------------------------------------------------------------------
__global__ void k_hist(const int* __restrict__ ei) {
    int e = blockIdx.x * blockDim.x + threadIdx.x;
    if (e < NE) atomicAdd(&g_deg[ei[NE + e]], 1);
}

// ---------------------------------------------------------------------------
// 2) exclusive scan over degrees (single block)
// ---------------------------------------------------------------------------
__global__ void __launch_bounds__(1024) k_scan() {
    __shared__ int bs[1024];
    const int t = threadIdx.x;
    const int SEG = (NN + 1023) / 1024;
    int start = t * SEG;
    int stop = start + SEG < NN ? start + SEG : NN;
    int s = 0;
    for (int i = start; i < stop; i++) s += g_deg[i];
    bs[t] = s;
    __syncthreads();
    for (int d = 1; d < 1024; d <<= 1) {
        int u = (t >= d) ? bs[t - d] : 0;
        __syncthreads();
        if (t >= d) bs[t] += u;
        __syncthreads();
    }
    int run = bs[t] - s;
    for (int i = start; i < stop; i++) {
        g_off[i] = run;
        g_cur[i] = run;
        run += g_deg[i];
    }
    if (t == 1023) g_off[NN] = run;
}

// ---------------------------------------------------------------------------
// 3) bucket edges by dst
// ---------------------------------------------------------------------------
__global__ void k_bucket(const int* __restrict__ ei) {
    int e = blockIdx.x * blockDim.x + threadIdx.x;
    if (e >= NE) return;
    int dst = ei[NE + e];
    int pos = atomicAdd(&g_cur[dst], 1);
    g_srcs[pos] = ei[e];
}

// ---------------------------------------------------------------------------
// 4) aggregate: one warp per node; emit fp16
// ---------------------------------------------------------------------------
__global__ void __launch_bounds__(256) k_agg(const float* __restrict__ x) {
    int w = (blockIdx.x * blockDim.x + threadIdx.x) >> 5;
    if (w >= NN) return;
    int lane = threadIdx.x & 31;

    float4 acc = reinterpret_cast<const float4*>(x + (size_t)w * DIN)[lane];
    int beg = g_off[w], end = g_off[w + 1];
    for (int base = beg; base < end; base += 32) {
        int n = end - base;
        if (n > 32) n = 32;
        int s = (lane < n) ? g_srcs[base + lane] : 0;
        #pragma unroll 4
        for (int j = 0; j < n; j++) {
            int src = __shfl_sync(0xffffffffu, s, j);
            float4 v = reinterpret_cast<const float4*>(x + (size_t)src * DIN)[lane];
            acc.x += v.x; acc.y += v.y; acc.z += v.z; acc.w += v.w;
        }
    }
    size_t idx = (size_t)w * DIN + lane * 4;
    __half2* phi = reinterpret_cast<__half2*>(g_xhi + idx);
    phi[0] = __halves2half2(__float2half_rn(acc.x), __float2half_rn(acc.y));
    phi[1] = __halves2half2(__float2half_rn(acc.z), __float2half_rn(acc.w));
}

// ---------------------------------------------------------------------------
// 5) W [K,N] -> W^T [N,K] fp16
// ---------------------------------------------------------------------------
__global__ void k_prep_w(const float* __restrict__ W, __half* __restrict__ hi,
                         int K, int N) {
    int i = blockIdx.x * blockDim.x + threadIdx.x;
    if (i >= K * N) return;
    int n = i / K, k = i % K;
    hi[i] = __float2half_rn(W[(size_t)k * N + n]);
}

// ---------------------------------------------------------------------------
// 6) GEMM1 single-shot: hmid = lrelu(A @ W1^T + b1) -> fp16.
//    K=128 loaded in one cp.async wave. CTA 128x128, 8 warps (4m x 2n),
//    2 CTAs/SM. Row pad 256B->272B (68 words = 4 mod 32, conflict-free ldsm).
// ---------------------------------------------------------------------------
#define A1_ROWB 272
#define A1_SZ (128 * A1_ROWB)        // 34816
#define G1_A 0
#define G1_B A1_SZ
#define G1_SMEM (2 * A1_SZ)          // 69632 -> 2 CTAs/SM

__global__ void __launch_bounds__(256, 2)
k_gemm1(const __half* __restrict__ Ah, const __half* __restrict__ Bh,
        const float* __restrict__ bias, __half* __restrict__ Chi) {
    extern __shared__ char smem[];
    const uint32_t sb = smem_u32(smem);
    const int tid = threadIdx.x;
    const int wid = tid >> 5;
    const int lane = tid & 31;
    const int warp_m = wid & 3;
    const int warp_n = wid >> 2;
    const int m0 = blockIdx.y * 128;
    const int n0 = blockIdx.x * 128;
    const int M = NN, K = DIN, ldc = DHID;

    #pragma unroll
    for (int it = 0; it < 8; it++) {
        int idx = tid + it * 256;            // 0..2047
        int row = idx >> 4;                  // 0..127
        int c = idx & 15;                    // 16B chunk within 256B row
        uint32_t soff = (uint32_t)(row * A1_ROWB + c * 16);
        int gmr = m0 + row;
        cp_async16(sb + G1_A + soff, Ah + (size_t)gmr * K + c * 8, gmr < M);
        int gnr = n0 + row;
        cp_async16(sb + G1_B + soff, Bh + (size_t)gnr * K + c * 8, true);
    }
    cp_commit();
    cp_wait0();
    __syncthreads();

    float acc[2][8][4];
    #pragma unroll
    for (int a = 0; a < 2; a++)
        #pragma unroll
        for (int b = 0; b < 8; b++)
            #pragma unroll
            for (int c = 0; c < 4; c++) acc[a][b][c] = 0.f;

    const uint32_t lrow = (uint32_t)(lane & 15);
    const uint32_t lchk = (uint32_t)(lane >> 4);

    #pragma unroll
    for (int ks = 0; ks < 8; ks++) {
        uint32_t a_hi[2][4];
        #pragma unroll
        for (int mt = 0; mt < 2; mt++) {
            uint32_t r = (uint32_t)(warp_m * 32 + mt * 16) + lrow;
            ldsm_x4(a_hi[mt], sb + G1_A + r * A1_ROWB + lchk * 16 + ks * 32);
        }
        #pragma unroll
        for (int np = 0; np < 4; np++) {
            uint32_t bh[4];
            uint32_t r = (uint32_t)(warp_n * 64 + np * 16) + lrow;
            ldsm_x4(bh, sb + G1_B + r * A1_ROWB + lchk * 16 + ks * 32);
            uint32_t b0h[2] = {bh[0], bh[2]}, b1h[2] = {bh[1], bh[3]};
            #pragma unroll
            for (int mt = 0; mt < 2; mt++) {
                hmma(acc[mt][2 * np],     a_hi[mt], b0h);
                hmma(acc[mt][2 * np + 1], a_hi[mt], b1h);
            }
        }
    }

    #pragma unroll
    for (int mt = 0; mt < 2; mt++) {
        int row = m0 + warp_m * 32 + mt * 16 + (lane >> 2);
        #pragma unroll
        for (int nt = 0; nt < 8; nt++) {
            int col = n0 + warp_n * 64 + nt * 8 + 2 * (lane & 3);
            float bx = bias[col], by = bias[col + 1];
            #pragma unroll
            for (int h = 0; h < 2; h++) {
                int r = row + h * 8;
                if (r >= M) continue;
                float v0 = acc[mt][nt][2 * h + 0] + bx;
                float v1 = acc[mt][nt][2 * h + 1] + by;
                v0 = v0 > 0.f ? v0 : 0.01f * v0;
                v1 = v1 > 0.f ? v1 : 0.01f * v1;
                *reinterpret_cast<__half2*>(Chi + (size_t)r * ldc + col) =
                    __halves2half2(__float2half_rn(v0), __float2half_rn(v1));
            }
        }
    }
}

// ---------------------------------------------------------------------------
// 7) GEMM2: h2 = lrelu(hmid @ W2^T + b2) -> fp32 + fused BN stats.
//    CTA 128x128, BK=32, 8 warps (4m x 2n), 3-stage ring, 2 CTAs/SM.
// ---------------------------------------------------------------------------
#define ROWB 80
#define MATB (128 * ROWB)
#define STAGEB (2 * MATB)            // A + B = 20480
#define SM_A 0
#define SM_B MATB
#define G2_SMEM (3 * STAGEB)         // 61440 -> 2 CTAs/SM

__global__ void __launch_bounds__(256, 2)
k_gemm2(const __half* __restrict__ Ah, const __half* __restrict__ Bh,
        const float* __restrict__ bias, float* __restrict__ Cf) {
    extern __shared__ char smem[];
    const uint32_t sb = smem_u32(smem);
    const int tid = threadIdx.x;
    const int wid = tid >> 5;
    const int lane = tid & 31;
    const int warp_m = wid & 3;
    const int warp_n = wid >> 2;
    const int m0 = blockIdx.y * 128;
    const int n0 = blockIdx.x * 128;
    const int M = NN, K = DHID, ldc = DOUT;

    float acc[2][8][4];
    #pragma unroll
    for (int a = 0; a < 2; a++)
        #pragma unroll
        for (int b = 0; b < 8; b++)
            #pragma unroll
            for (int c = 0; c < 4; c++) acc[a][b][c] = 0.f;

    const int nchunks = K >> 5;

    auto load_chunk = [&](int ch) {
        const int k0 = ch << 5;
        const uint32_t stg = sb + (ch % 3) * STAGEB;
        #pragma unroll
        for (int it = 0; it < 2; it++) {
            int idx = tid + it * 256;
            int row = idx >> 2;
            int c = idx & 3;
            uint32_t soff = (uint32_t)(row * ROWB + c * 16);
            int gmr = m0 + row;
            cp_async16(stg + SM_A + soff, Ah + (size_t)gmr * K + k0 + c * 8, gmr < M);
            int gnr = n0 + row;
            cp_async16(stg + SM_B + soff, Bh + (size_t)gnr * K + k0 + c * 8, true);
        }
        cp_commit();
    };

    load_chunk(0);
    load_chunk(1);

    for (int ch = 0; ch < nchunks; ch++) {
        if (ch + 1 < nchunks) cp_wait1(); else cp_wait0();
        __syncthreads();

        const uint32_t stg = sb + (ch % 3) * STAGEB;
        const uint32_t lrow = (uint32_t)(lane & 15);
        const uint32_t lchk = (uint32_t)(lane >> 4);

        #pragma unroll
        for (int ks = 0; ks < 2; ks++) {
            uint32_t a_hi[2][4];
            #pragma unroll
            for (int mt = 0; mt < 2; mt++) {
                uint32_t r = (uint32_t)(warp_m * 32 + mt * 16) + lrow;
                ldsm_x4(a_hi[mt], stg + SM_A + r * ROWB + lchk * 16 + ks * 32);
            }
            #pragma unroll
            for (int np = 0; np < 4; np++) {
                uint32_t bh[4];
                uint32_t r = (uint32_t)(warp_n * 64 + np * 16) + lrow;
                ldsm_x4(bh, stg + SM_B + r * ROWB + lchk * 16 + ks * 32);
                uint32_t b0h[2] = {bh[0], bh[2]}, b1h[2] = {bh[1], bh[3]};
                #pragma unroll
                for (int mt = 0; mt < 2; mt++) {
                    hmma(acc[mt][2 * np],     a_hi[mt], b0h);
                    hmma(acc[mt][2 * np + 1], a_hi[mt], b1h);
                }
            }
        }
        if (ch + 2 < nchunks) load_chunk(ch + 2);
    }

    // Epilogue: bias + lrelu + store + BN stats
    float scol[8][2];
    float qcol[8][2];
    #pragma unroll
    for (int nt = 0; nt < 8; nt++) {
        scol[nt][0] = scol[nt][1] = 0.f;
        qcol[nt][0] = qcol[nt][1] = 0.f;
    }

    #pragma unroll
    for (int mt = 0; mt < 2; mt++) {
        int row = m0 + warp_m * 32 + mt * 16 + (lane >> 2);
        #pragma unroll
        for (int nt = 0; nt < 8; nt++) {
            int col = n0 + warp_n * 64 + nt * 8 + 2 * (lane & 3);
            float bx = bias[col], by = bias[col + 1];
            #pragma unroll
            for (int h = 0; h < 2; h++) {
                int r = row + h * 8;
                if (r >= M) continue;
                float v0 = acc[mt][nt][2 * h + 0] + bx;
                float v1 = acc[mt][nt][2 * h + 1] + by;
                v0 = v0 > 0.f ? v0 : 0.01f * v0;
                v1 = v1 > 0.f ? v1 : 0.01f * v1;
                *reinterpret_cast<float2*>(Cf + (size_t)r * ldc + col) =
                    make_float2(v0, v1);
                scol[nt][0] += v0; qcol[nt][0] += v0 * v0;
                scol[nt][1] += v1; qcol[nt][1] += v1 * v1;
            }
        }
    }

    {
        float* sarr = reinterpret_cast<float*>(smem);
        float* qarr = sarr + 128;
        __syncthreads();
        if (tid < 128) { sarr[tid] = 0.f; qarr[tid] = 0.f; }
        __syncthreads();
        #pragma unroll
        for (int nt = 0; nt < 8; nt++) {
            float s0 = scol[nt][0], s1 = scol[nt][1];
            float q0 = qcol[nt][0], q1 = qcol[nt][1];
            #pragma unroll
            for (int o = 4; o < 32; o <<= 1) {
                s0 += __shfl_xor_sync(0xffffffffu, s0, o);
                s1 += __shfl_xor_sync(0xffffffffu, s1, o);
                q0 += __shfl_xor_sync(0xffffffffu, q0, o);
                q1 += __shfl_xor_sync(0xffffffffu, q1, o);
            }
            if (lane < 4) {
                int c = warp_n * 64 + nt * 8 + 2 * lane;
                atomicAdd(&sarr[c], s0);
                atomicAdd(&sarr[c + 1], s1);
                atomicAdd(&qarr[c], q0);
                atomicAdd(&qarr[c + 1], q1);
            }
        }
        __syncthreads();
        if (tid < 128) {
            atomicAdd(&g_sum[n0 + tid], sarr[tid]);
            atomicAdd(&g_sumsq[n0 + tid], qarr[tid]);
        }
    }
}

// ---------------------------------------------------------------------------
// 8) normalize with inline BN finalize
// ---------------------------------------------------------------------------
__global__ void __launch_bounds__(256) k_normalize(float* __restrict__ out,
                                                   const float* __restrict__ gamma,
                                                   const float* __restrict__ beta) {
    __shared__ float4 s_sc[DOUT / 4];
    __shared__ float4 s_sh[DOUT / 4];
    const int tid = threadIdx.x;
    if (tid < DOUT / 4) {
        const float invn = 1.0f / (float)NN;
        float4 sc, sh;
        #pragma unroll
        for (int k = 0; k < 4; k++) {
            int c = tid * 4 + k;
            float mean = g_sum[c] * invn;
            float var = g_sumsq[c] * invn - mean * mean;
            float rstd = rsqrtf(var + 1e-5f);
            float s = gamma[c] * rstd;
            (&sc.x)[k] = s;
            (&sh.x)[k] = beta[c] - mean * s;
        }
        s_sc[tid] = sc;
        s_sh[tid] = sh;
    }
    __syncthreads();

    int i = blockIdx.x * blockDim.x + tid;
    const int n4 = NN * DOUT / 4;
    if (i >= n4) return;
    int c4 = i & (DOUT / 4 - 1);
    float4 v = reinterpret_cast<const float4*>(g_h2)[i];
    float4 sc = s_sc[c4];
    float4 sh = s_sh[c4];
    v.x = v.x * sc.x + sh.x;
    v.y = v.y * sc.y + sh.y;
    v.z = v.z * sc.z + sh.z;
    v.w = v.w * sc.w + sh.w;
    reinterpret_cast<float4*>(out)[i] = v;
}

// ---------------------------------------------------------------------------
extern "C" void kernel_launch(void* const* d_in, const int* in_sizes, int n_in,
                              void* d_out, int out_size) {
    const float* x     = (const float*)d_in[0];
    const int*   ei    = (const int*)d_in[1];
    const float* W1    = (const float*)d_in[2];
    const float* b1    = (const float*)d_in[3];
    const float* W2    = (const float*)d_in[4];
    const float* b2    = (const float*)d_in[5];
    const float* gamma = (const float*)d_in[6];
    const float* beta  = (const float*)d_in[7];
    float* out = (float*)d_out;

    __half *xhi, *mhi, *w1hi, *w2hi;
    float* h2;
    cudaGetSymbolAddress((void**)&xhi, g_xhi);
    cudaGetSymbolAddress((void**)&mhi, g_mhi);
    cudaGetSymbolAddress((void**)&w1hi, g_w1hi);
    cudaGetSymbolAddress((void**)&w2hi, g_w2hi);
    cudaGetSymbolAddress((void**)&h2, g_h2);

    cudaFuncSetAttribute(k_gemm1,
                         cudaFuncAttributeMaxDynamicSharedMemorySize, G1_SMEM);
    cudaFuncSetAttribute(k_gemm2,
                         cudaFuncAttributeMaxDynamicSharedMemorySize, G2_SMEM);

    // CSR build + aggregate (+fp16 convert)
    k_zero<<<(NN + 255) / 256, 256>>>();
    k_hist<<<(NE + 255) / 256, 256>>>(ei);
    k_scan<<<1, 1024>>>();
    k_bucket<<<(NE + 255) / 256, 256>>>(ei);
    k_agg<<<(NN * 32 + 255) / 256, 256>>>(x);

    // weight prep
    k_prep_w<<<(DIN * DHID + 255) / 256, 256>>>(W1, w1hi, DIN, DHID);
    k_prep_w<<<(DHID * DOUT + 255) / 256, 256>>>(W2, w2hi, DHID, DOUT);

    // GEMM1: [50000x128]@[128x512] -> fp16 (single-shot K)
    {
        dim3 grid(DHID / 128, (NN + 127) / 128);
        k_gemm1<<<grid, 256, G1_SMEM>>>(xhi, w1hi, b1, mhi);
    }
    // GEMM2: [50000x512]@[512x256] -> fp32 (+fused BN stats)
    {
        dim3 grid(DOUT / 128, (NN + 127) / 128);
        k_gemm2<<<grid, 256, G2_SMEM>>>(mhi, w2hi, b2, h2);
    }
    // normalize (inline BN finalize)
    k_normalize<<<(NN * DOUT / 4 + 255) / 256, 256>>>(out, gamma, beta);
}